// round 9
// baseline (speedup 1.0000x reference)
#include <cuda_runtime.h>
#include <math.h>

// Problem constants
#define BATCH   64
#define IN_D    256
#define MEM_D   128
#define NSLOT   4096
#define CPB     8                  // chunks (blocks) per batch -> single wave
#define CHUNK   (NSLOT / CPB)      // 512 rows per block
#define KQ      8                  // K slices in proj (32 each)
// Skip threshold: rw_n <= e^{rl_n - m2_local}; drop if < 1e-10.
// Worst-case dropped mass < 4096e-10 ~ 4e-7 << 1e-3 tolerance.
#define SKIP_EPS 1e-10f

// -------- scratch (no device allocations allowed) --------
__device__ float g_pp[3 * BATCH * KQ * MEM_D]; // proj partials [m][b][kq][o]
__device__ float g_v [BATCH * MEM_D];          // finalized v (written by fused ch==0)
__device__ float g_s [BATCH];
__device__ float g_rop[BATCH * CPB * MEM_D];   // per-chunk read_out partials

__device__ float g_pm1[BATCH * CPB];
__device__ float g_pz1[BATCH * CPB];
__device__ float g_pm2[BATCH * CPB];
__device__ float g_pz2[BATCH * CPB];
__device__ float g_ps2[BATCH * CPB];
__device__ int   g_cnt1[BATCH];                // zero-init; reset by out_kernel
__device__ int   g_cnt2[BATCH];

__device__ __forceinline__ float warpSum(float v) {
#pragma unroll
    for (int o = 16; o; o >>= 1) v += __shfl_xor_sync(0xffffffffu, v, o);
    return v;
}
__device__ __forceinline__ float warpMax(float v) {
#pragma unroll
    for (int o = 16; o; o >>= 1) v = fmaxf(v, __shfl_xor_sync(0xffffffffu, v, o));
    return v;
}
// block reduce for 256 threads (8 warps)
__device__ __forceinline__ float blockSum(float v, float* sred) {
    v = warpSum(v);
    if ((threadIdx.x & 31) == 0) sred[threadIdx.x >> 5] = v;
    __syncthreads();
    float r = sred[0];
#pragma unroll
    for (int i = 1; i < 8; i++) r += sred[i];
    __syncthreads();
    return r;
}
__device__ __forceinline__ float blockMax(float v, float* sred) {
    v = warpMax(v);
    if ((threadIdx.x & 31) == 0) sred[threadIdx.x >> 5] = v;
    __syncthreads();
    float r = sred[0];
#pragma unroll
    for (int i = 1; i < 8; i++) r = fmaxf(r, sred[i]);
    __syncthreads();
    return r;
}

// ---------------------------------------------------------------------------
// Kernel 1: projection PARTIALS. grid = 1536 (3 x 64 x 8 K-slices), blk 128.
// 32-load chains, 4 independent accumulators.
// ---------------------------------------------------------------------------
__global__ void __launch_bounds__(128)
proj_kernel(const float* __restrict__ x,
            const float* __restrict__ Ww,
            const float* __restrict__ Wq,
            const float* __restrict__ Wr) {
    const int m   = blockIdx.x >> 9;          // 0..2
    const int rem = blockIdx.x & 511;
    const int b   = rem >> 3;                 // 0..63
    const int kq  = rem & 7;                  // K slice
    const int t   = threadIdx.x;              // 0..127 (output column)

    const float* W = (m == 0) ? Ww : ((m == 1) ? Wq : Wr);
    const int k0 = kq * 32;

    __shared__ float sx[32];
    if (t < 32) sx[t] = x[b * IN_D + k0 + t];
    __syncthreads();

    float a0 = 0.f, a1 = 0.f, a2 = 0.f, a3 = 0.f;
    const float* Wc = W + (size_t)k0 * MEM_D + t;
#pragma unroll
    for (int k = 0; k < 32; k += 4) {
        a0 = fmaf(sx[k + 0], Wc[(k + 0) * MEM_D], a0);
        a1 = fmaf(sx[k + 1], Wc[(k + 1) * MEM_D], a1);
        a2 = fmaf(sx[k + 2], Wc[(k + 2) * MEM_D], a2);
        a3 = fmaf(sx[k + 3], Wc[(k + 3) * MEM_D], a3);
    }
    g_pp[(((m * BATCH) + b) * KQ + kq) * MEM_D + t] = (a0 + a1) + (a2 + a3);
}

// ---------------------------------------------------------------------------
// Kernel 2: FUSED dots + dual-softmax + SPARSE accumulation, SINGLE WAVE.
// grid = 512 (64 x 8 chunks), block 256, 4 blocks/SM -> all resident.
// Phase 2 only touches rows whose conservative weight bound e^{rl-m2_loc}
// exceeds SKIP_EPS (compacted list). Barrier-2 arrive before / wait after.
// ---------------------------------------------------------------------------
__global__ void __launch_bounds__(256, 4)
fused_kernel(const float* __restrict__ mem,
             const float* __restrict__ bw,
             const float* __restrict__ bq,
             const float* __restrict__ br) {
    const int b  = blockIdx.x >> 3;
    const int ch = blockIdx.x & 7;
    const int bi = blockIdx.x;
    const int t  = threadIdx.x;
    const int lane = t & 31, w = t >> 5;      // 8 warps
    const int s = lane & 7, rsub = lane >> 3; // quarter-warp layout (phase 1)

    __shared__ float  sd1[CHUNK];             // d1 -> ww
    __shared__ float  sd2[CHUNK];             // d2 -> rl
    __shared__ float  swq[MEM_D];
    __shared__ float  srq[MEM_D];
    __shared__ float  sv [MEM_D];
    __shared__ float  sred[8];
    __shared__ float  sbc[2];
    __shared__ int    slist[CHUNK];
    __shared__ float  scoef[CHUNK];
    __shared__ int    scnt;
    __shared__ float4 racc[256];

    if (t < MEM_D) {
        const float* pv = g_pp + ((0 * BATCH + b) * KQ) * MEM_D + t;
        const float* pq = g_pp + ((1 * BATCH + b) * KQ) * MEM_D + t;
        const float* pr = g_pp + ((2 * BATCH + b) * KQ) * MEM_D + t;
        float av = bw[t], aq = bq[t], ar = br[t];
#pragma unroll
        for (int j = 0; j < KQ; j++) {
            av += pv[j * MEM_D];
            aq += pq[j * MEM_D];
            ar += pr[j * MEM_D];
        }
        sv[t] = av; swq[t] = aq; srq[t] = ar;
        if (ch == 0) g_v[b * MEM_D + t] = av;     // publish for out_kernel
    }
    if (t == 0) scnt = 0;
    __syncthreads();

    // per-thread query slices (cols (j*8+s)*4 .. +3)
    float4 q4[4], r4[4];
#pragma unroll
    for (int j = 0; j < 4; j++) {
        q4[j] = reinterpret_cast<const float4*>(swq)[j * 8 + s];
        r4[j] = reinterpret_cast<const float4*>(srq)[j * 8 + s];
    }

    const float4* mb = reinterpret_cast<const float4*>(mem) +
                       ((size_t)b * NSLOT + (size_t)ch * CHUNK) * 32;

    // ---- Phase 1: coalesced dots d1 = mem.wq, d2 = mem.rq ----
#pragma unroll 2
    for (int it = 0; it < 16; it++) {
        const int r0 = it * 32 + w * 4 + rsub;
        const float4* grow = mb + (size_t)r0 * 32;
        float a = 0.0f, c = 0.0f;
#pragma unroll
        for (int j = 0; j < 4; j++) {
            const float4 m = grow[j * 8 + s];
            a = fmaf(m.x, q4[j].x, a); a = fmaf(m.y, q4[j].y, a);
            a = fmaf(m.z, q4[j].z, a); a = fmaf(m.w, q4[j].w, a);
            c = fmaf(m.x, r4[j].x, c); c = fmaf(m.y, r4[j].y, c);
            c = fmaf(m.z, r4[j].z, c); c = fmaf(m.w, r4[j].w, c);
        }
#pragma unroll
        for (int o = 4; o; o >>= 1) {         // reduce over s (8 lanes)
            a += __shfl_xor_sync(0xffffffffu, a, o);
            c += __shfl_xor_sync(0xffffffffu, c, o);
        }
        if (s == 0) { sd1[r0] = a; sd2[r0] = c; }
    }

    // qv = v . rq
    float qp = (t < MEM_D) ? sv[t] * srq[t] : 0.0f;
    __syncthreads();                          // publish sd1/sd2
    const float qv = blockSum(qp, sred);

    // ---- local write-softmax partials (2 elems per thread) ----
    const float m1 = blockMax(fmaxf(sd1[t], sd1[t + 256]), sred);
    const float z1 = blockSum(__expf(sd1[t] - m1) + __expf(sd1[t + 256] - m1),
                              sred);

    // ---- cross-chunk combine #1 (full wait: ww needs global M1/Z1) ----
    if (t == 0) {
        *(volatile float*)&g_pm1[bi] = m1;
        *(volatile float*)&g_pz1[bi] = z1;
        __threadfence();
        atomicAdd(&g_cnt1[b], 1);
        while (atomicAdd(&g_cnt1[b], 0) < CPB) __nanosleep(32);
        __threadfence();
    }
    __syncthreads();
    if (t < 32) {
        const float pm = (t < CPB) ? *(volatile float*)&g_pm1[b * CPB + t] : -1e30f;
        const float pz = (t < CPB) ? *(volatile float*)&g_pz1[b * CPB + t] : 0.0f;
        const float M  = warpMax(pm);
        const float Z  = warpSum(pz * __expf(pm - M));
        if (t == 0) { sbc[0] = M; sbc[1] = 1.0f / Z; }
    }
    __syncthreads();
    const float M1 = sbc[0], invZ1 = sbc[1];

    // ---- ww (exact), read-logits; local read-softmax partials ----
    float m2l = -1e30f;
#pragma unroll
    for (int i = 0; i < 2; i++) {
        const int n = t + i * 256;
        const float ww = __expf(sd1[n] - M1) * invZ1;
        const float d2v = sd2[n];
        const float rl = d2v - ww * (d2v - qv);
        sd1[n] = ww;
        sd2[n] = rl;
        m2l = fmaxf(m2l, rl);
    }
    const float m2 = blockMax(m2l, sred);
    float lz2 = 0.0f, ls2 = 0.0f;
#pragma unroll
    for (int i = 0; i < 2; i++) {
        const int n = t + i * 256;
        const float e = __expf(sd2[n] - m2);
        lz2 += e;
        ls2 += e * sd1[n];
    }
    const float z2 = blockSum(lz2, sred);
    const float s2 = blockSum(ls2, sred);

    // ---- barrier 2: ARRIVE ONLY (wait deferred past phase 2) ----
    if (t == 0) {
        *(volatile float*)&g_pm2[bi] = m2;
        *(volatile float*)&g_pz2[bi] = z2;
        *(volatile float*)&g_ps2[bi] = s2;
        __threadfence();
        atomicAdd(&g_cnt2[b], 1);
    }

    // ---- compact significant rows: c'_n = e^{rl-m2}(1-ww) > EPS ----
#pragma unroll
    for (int i = 0; i < 2; i++) {
        const int n = t + i * 256;
        const float eb = __expf(sd2[n] - m2);         // >= c'_n, <= rw bound
        if (eb > SKIP_EPS) {
            const int idx = atomicAdd(&scnt, 1);
            slist[idx] = n;
            scoef[idx] = eb * (1.0f - sd1[n]);
        }
    }
    __syncthreads();
    const int cnt = scnt;

    // ---- Phase 2: SPARSE weighted sum, one coalesced row-load per kept row ----
    float4 acc = make_float4(0.f, 0.f, 0.f, 0.f);
    for (int i = w; i < cnt; i += 8) {
        const int   n  = slist[i];
        const float cv = scoef[i];
        const float4 m = __ldcs(mb + (size_t)n * 32 + lane);
        acc.x = fmaf(cv, m.x, acc.x);
        acc.y = fmaf(cv, m.y, acc.y);
        acc.z = fmaf(cv, m.z, acc.z);
        acc.w = fmaf(cv, m.w, acc.w);
    }
    racc[w * 32 + lane] = acc;

    // ---- barrier 2: WAIT + combine (overlapped with peers' phase 2) ----
    if (t == 0) {
        while (atomicAdd(&g_cnt2[b], 0) < CPB) __nanosleep(32);
        __threadfence();
    }
    __syncthreads();
    if (t < 32) {
        const float pm = (t < CPB) ? *(volatile float*)&g_pm2[b * CPB + t] : -1e30f;
        const float pz = (t < CPB) ? *(volatile float*)&g_pz2[b * CPB + t] : 0.0f;
        const float ps = (t < CPB) ? *(volatile float*)&g_ps2[b * CPB + t] : 0.0f;
        const float M  = warpMax(pm);
        const float e  = __expf(pm - M);
        const float Z  = warpSum(pz * e);
        const float S  = warpSum(ps * e);
        if (t == 0) {
            sbc[0] = M; sbc[1] = 1.0f / Z;
            if (ch == 0) g_s[b] = S / Z;
        }
    }
    __syncthreads();
    const float scale = __expf(m2 - sbc[0]) * sbc[1];   // e^{m2-M2}/Z2

    if (t < 32) {
        float4 ssum = racc[t];
#pragma unroll
        for (int w2 = 1; w2 < 8; w2++) {
            const float4 u = racc[w2 * 32 + t];
            ssum.x += u.x; ssum.y += u.y; ssum.z += u.z; ssum.w += u.w;
        }
        ssum.x *= scale; ssum.y *= scale; ssum.z *= scale; ssum.w *= scale;
        reinterpret_cast<float4*>(g_rop + (size_t)bi * MEM_D)[t] = ssum;
    }
}

// ---------------------------------------------------------------------------
// Kernel 3: sum chunk partials, add s*v, final projection; reset counters.
// grid 64, block 512 (2 threads per output, K halves).
// ---------------------------------------------------------------------------
__global__ void __launch_bounds__(512)
out_kernel(const float* __restrict__ Wro,
           const float* __restrict__ bro,
           float* __restrict__ out) {
    const int b = blockIdx.x;
    const int t = threadIdx.x;               // 0..511
    __shared__ float sr[MEM_D];
    __shared__ float so[512];
    if (t < MEM_D) {
        float acc = g_s[b] * g_v[b * MEM_D + t];
#pragma unroll
        for (int c = 0; c < CPB; c++)
            acc += g_rop[((size_t)b * CPB + c) * MEM_D + t];
        sr[t] = acc;
    }
    if (t == 0) { g_cnt1[b] = 0; g_cnt2[b] = 0; }   // reset for next replay
    __syncthreads();

    const int o = t & 255;
    const int h = t >> 8;
    float acc = 0.0f;
    const int d0 = h * 64;
#pragma unroll 8
    for (int d = 0; d < 64; d++)
        acc = fmaf(sr[d0 + d], Wro[(d0 + d) * IN_D + o], acc);
    so[t] = acc;
    __syncthreads();
    if (t < IN_D)
        out[b * IN_D + t] = so[t] + so[256 + t] + bro[t];
}

// ---------------------------------------------------------------------------
extern "C" void kernel_launch(void* const* d_in, const int* in_sizes, int n_in,
                              void* d_out, int out_size) {
    const float* x   = (const float*)d_in[0];
    const float* mem = (const float*)d_in[1];
    const float* Ww  = (const float*)d_in[2];
    const float* bw  = (const float*)d_in[3];
    const float* Wq  = (const float*)d_in[4];
    const float* bq  = (const float*)d_in[5];
    const float* Wr  = (const float*)d_in[6];
    const float* br  = (const float*)d_in[7];
    const float* Wro = (const float*)d_in[8];
    const float* bro = (const float*)d_in[9];
    float* out = (float*)d_out;

    proj_kernel<<<3 * BATCH * KQ, 128>>>(x, Ww, Wq, Wr);
    fused_kernel<<<BATCH * CPB, 256>>>(mem, bw, bq, br);
    out_kernel<<<BATCH, 512>>>(Wro, bro, out);
}

// round 10
// speedup vs baseline: 1.0044x; 1.0044x over previous
#include <cuda_runtime.h>
#include <math.h>

// Problem constants
#define BATCH   64
#define IN_D    256
#define MEM_D   128
#define NSLOT   4096
#define CPB     8                  // chunks (blocks) per batch -> single wave
#define CHUNK   (NSLOT / CPB)      // 512 rows per block
#define KSL     32                 // K-slice per block in proj stage
// Skip threshold: rw_n <= e^{rl_n - m2_local}; drop if < 1e-10.
// Worst-case dropped mass < 4096e-10 ~ 4e-7 << 1e-3 tolerance.
#define SKIP_EPS 1e-10f

// -------- scratch (no device allocations allowed) --------
__device__ float g_pp[3 * BATCH * CPB * MEM_D]; // proj partials [m][b][ch][o]
__device__ float g_rop[BATCH * CPB * MEM_D];    // per-chunk read_out partials

__device__ int g_cnt0[BATCH];   // proj barrier      (zero-init; reset by ch0)
__device__ int g_cnt1[BATCH];   // write-softmax barrier
__device__ int g_cnt2[BATCH];   // read-softmax barrier (deferred wait)
__device__ int g_cnt3[BATCH];   // rop-complete barrier

__device__ __forceinline__ float warpSum(float v) {
#pragma unroll
    for (int o = 16; o; o >>= 1) v += __shfl_xor_sync(0xffffffffu, v, o);
    return v;
}
__device__ __forceinline__ float warpMax(float v) {
#pragma unroll
    for (int o = 16; o; o >>= 1) v = fmaxf(v, __shfl_xor_sync(0xffffffffu, v, o));
    return v;
}
// block reduce for 256 threads (8 warps)
__device__ __forceinline__ float blockSum(float v, float* sred) {
    v = warpSum(v);
    if ((threadIdx.x & 31) == 0) sred[threadIdx.x >> 5] = v;
    __syncthreads();
    float r = sred[0];
#pragma unroll
    for (int i = 1; i < 8; i++) r += sred[i];
    __syncthreads();
    return r;
}
__device__ __forceinline__ float blockMax(float v, float* sred) {
    v = warpMax(v);
    if ((threadIdx.x & 31) == 0) sred[threadIdx.x >> 5] = v;
    __syncthreads();
    float r = sred[0];
#pragma unroll
    for (int i = 1; i < 8; i++) r = fmaxf(r, sred[i]);
    __syncthreads();
    return r;
}

// ---------------------------------------------------------------------------
// MEGA kernel: proj + dots + dual-softmax + sparse accumulation + output.
// grid = 512 (64 batches x 8 chunks), block 256, 4 blocks/SM -> single wave,
// so all per-batch counter barriers are deadlock-free.
// ---------------------------------------------------------------------------
__global__ void __launch_bounds__(256, 4)
mega_kernel(const float* __restrict__ mem,
            const float* __restrict__ x,
            const float* __restrict__ Ww, const float* __restrict__ bw,
            const float* __restrict__ Wq, const float* __restrict__ bq,
            const float* __restrict__ Wr, const float* __restrict__ br,
            const float* __restrict__ Wro, const float* __restrict__ bro,
            float* __restrict__ out) {
    const int b  = blockIdx.x >> 3;
    const int ch = blockIdx.x & 7;
    const int bi = blockIdx.x;
    const int t  = threadIdx.x;
    const int lane = t & 31, w = t >> 5;      // 8 warps
    const int s = lane & 7, rsub = lane >> 3; // quarter-warp layout (phase 1)

    __shared__ float  sd1[CHUNK];             // d1 -> ww ; later reused as sr
    __shared__ float  sd2[CHUNK];             // d2 -> rl
    __shared__ float  swq[MEM_D];
    __shared__ float  srq[MEM_D];
    __shared__ float  sv [MEM_D];
    __shared__ float  sred[8];
    __shared__ float  sbc[3];
    __shared__ int    slist[CHUNK];
    __shared__ float  scoef[CHUNK];
    __shared__ int    scnt;
    __shared__ float4 racc[256];
    __shared__ float  sx[KSL];

    // ================= Stage 0: projection K-slice =================
    if (t < KSL) sx[t] = x[b * IN_D + ch * KSL + t];
    if (t == 0) scnt = 0;
    __syncthreads();

    {
        const int o = t & 127;
        const int k0 = ch * KSL;
        const float* WA = (t < 128) ? Ww : Wq;   // t<128: Ww col o; else Wq col o
        float aA = 0.f, aB = 0.f;
#pragma unroll 8
        for (int k = 0; k < KSL; k++) {
            const float xv = sx[k];
            aA = fmaf(xv, WA[(k0 + k) * MEM_D + o], aA);
            if (t < 128) aB = fmaf(xv, Wr[(k0 + k) * MEM_D + o], aB);
        }
        const int mA = (t < 128) ? 0 : 1;
        g_pp[(((mA * BATCH) + b) * CPB + ch) * MEM_D + o] = aA;
        if (t < 128)
            g_pp[(((2 * BATCH) + b) * CPB + ch) * MEM_D + o] = aB;
    }
    __syncthreads();                          // all proj stores issued
    // barrier 0: wait for all 8 K-slices of this batch
    if (t == 0) {
        __threadfence();
        atomicAdd(&g_cnt0[b], 1);
        while (atomicAdd(&g_cnt0[b], 0) < CPB) __nanosleep(32);
        __threadfence();
    }
    __syncthreads();

    // gather queries: sum 8 slice-partials + bias
    if (t < MEM_D) {
        float av = bw[t], aq = bq[t], ar = br[t];
        const float* pv = g_pp + ((0 * BATCH + b) * CPB) * MEM_D + t;
        const float* pq = g_pp + ((1 * BATCH + b) * CPB) * MEM_D + t;
        const float* pr = g_pp + ((2 * BATCH + b) * CPB) * MEM_D + t;
#pragma unroll
        for (int j = 0; j < CPB; j++) {
            av += __ldcg(pv + j * MEM_D);
            aq += __ldcg(pq + j * MEM_D);
            ar += __ldcg(pr + j * MEM_D);
        }
        sv[t] = av; swq[t] = aq; srq[t] = ar;
    }
    __syncthreads();

    // per-thread query slices (cols (j*8+s)*4 .. +3)
    float4 q4[4], r4[4];
#pragma unroll
    for (int j = 0; j < 4; j++) {
        q4[j] = reinterpret_cast<const float4*>(swq)[j * 8 + s];
        r4[j] = reinterpret_cast<const float4*>(srq)[j * 8 + s];
    }

    const float4* mb = reinterpret_cast<const float4*>(mem) +
                       ((size_t)b * NSLOT + (size_t)ch * CHUNK) * 32;

    // ================= Phase 1: coalesced dots =================
#pragma unroll 2
    for (int it = 0; it < 16; it++) {
        const int r0 = it * 32 + w * 4 + rsub;
        const float4* grow = mb + (size_t)r0 * 32;
        float a = 0.0f, c = 0.0f;
#pragma unroll
        for (int j = 0; j < 4; j++) {
            const float4 m = grow[j * 8 + s];
            a = fmaf(m.x, q4[j].x, a); a = fmaf(m.y, q4[j].y, a);
            a = fmaf(m.z, q4[j].z, a); a = fmaf(m.w, q4[j].w, a);
            c = fmaf(m.x, r4[j].x, c); c = fmaf(m.y, r4[j].y, c);
            c = fmaf(m.z, r4[j].z, c); c = fmaf(m.w, r4[j].w, c);
        }
#pragma unroll
        for (int o = 4; o; o >>= 1) {         // reduce over s (8 lanes)
            a += __shfl_xor_sync(0xffffffffu, a, o);
            c += __shfl_xor_sync(0xffffffffu, c, o);
        }
        if (s == 0) { sd1[r0] = a; sd2[r0] = c; }
    }

    // qv = v . rq
    float qp = (t < MEM_D) ? sv[t] * srq[t] : 0.0f;
    __syncthreads();                          // publish sd1/sd2
    const float qv = blockSum(qp, sred);

    // ---- local write-softmax partials ----
    const float m1 = blockMax(fmaxf(sd1[t], sd1[t + 256]), sred);
    const float z1 = blockSum(__expf(sd1[t] - m1) + __expf(sd1[t + 256] - m1),
                              sred);

    // ---- barrier 1: full wait (ww needs global M1/Z1) ----
    if (t == 0) {
        *(volatile float*)&g_pp[bi] = 0.0f;   // (touch nothing; placeholder no)
    }
    // publish partials in dedicated slots of g_pp tail? use separate arrays:
    // reuse g_rop as partial store is unsafe; use static arrays below.
    {
        __shared__ float dummy;               // keep structure simple
        (void)dummy;
    }
    // partial publish via g_pm/g_pz arrays
    {
        static __device__ float g_pm1[BATCH * CPB];
        static __device__ float g_pz1[BATCH * CPB];
        if (t == 0) {
            *(volatile float*)&g_pm1[bi] = m1;
            *(volatile float*)&g_pz1[bi] = z1;
            __threadfence();
            atomicAdd(&g_cnt1[b], 1);
            while (atomicAdd(&g_cnt1[b], 0) < CPB) __nanosleep(32);
            __threadfence();
        }
        __syncthreads();
        if (t < 32) {
            const float pm = (t < CPB) ? *(volatile float*)&g_pm1[b * CPB + t]
                                       : -1e30f;
            const float pz = (t < CPB) ? *(volatile float*)&g_pz1[b * CPB + t]
                                       : 0.0f;
            const float M  = warpMax(pm);
            const float Z  = warpSum(pz * __expf(pm - M));
            if (t == 0) { sbc[0] = M; sbc[1] = 1.0f / Z; }
        }
        __syncthreads();
    }
    const float M1 = sbc[0], invZ1 = sbc[1];

    // ---- ww (exact), read-logits; local read-softmax partials ----
    float m2l = -1e30f;
#pragma unroll
    for (int i = 0; i < 2; i++) {
        const int n = t + i * 256;
        const float ww = __expf(sd1[n] - M1) * invZ1;
        const float d2v = sd2[n];
        const float rl = d2v - ww * (d2v - qv);
        sd1[n] = ww;
        sd2[n] = rl;
        m2l = fmaxf(m2l, rl);
    }
    const float m2 = blockMax(m2l, sred);
    float lz2 = 0.0f, ls2 = 0.0f;
#pragma unroll
    for (int i = 0; i < 2; i++) {
        const int n = t + i * 256;
        const float e = __expf(sd2[n] - m2);
        lz2 += e;
        ls2 += e * sd1[n];
    }
    const float z2 = blockSum(lz2, sred);
    const float s2 = blockSum(ls2, sred);

    // ---- barrier 2: ARRIVE ONLY (wait deferred past phase 2) ----
    static __device__ float g_pm2[BATCH * CPB];
    static __device__ float g_pz2[BATCH * CPB];
    static __device__ float g_ps2[BATCH * CPB];
    if (t == 0) {
        *(volatile float*)&g_pm2[bi] = m2;
        *(volatile float*)&g_pz2[bi] = z2;
        *(volatile float*)&g_ps2[bi] = s2;
        __threadfence();
        atomicAdd(&g_cnt2[b], 1);
    }

    // ---- compact significant rows: bound e^{rl-m2} > EPS ----
#pragma unroll
    for (int i = 0; i < 2; i++) {
        const int n = t + i * 256;
        const float eb = __expf(sd2[n] - m2);
        if (eb > SKIP_EPS) {
            const int idx = atomicAdd(&scnt, 1);
            slist[idx] = n;
            scoef[idx] = eb * (1.0f - sd1[n]);
        }
    }
    __syncthreads();
    const int cnt = scnt;

    // ---- Phase 2: SPARSE weighted sum (one coalesced row-load per row) ----
    float4 acc = make_float4(0.f, 0.f, 0.f, 0.f);
    for (int i = w; i < cnt; i += 8) {
        const int   n  = slist[i];
        const float cv = scoef[i];
        const float4 m = __ldcs(mb + (size_t)n * 32 + lane);
        acc.x = fmaf(cv, m.x, acc.x);
        acc.y = fmaf(cv, m.y, acc.y);
        acc.z = fmaf(cv, m.z, acc.z);
        acc.w = fmaf(cv, m.w, acc.w);
    }
    racc[w * 32 + lane] = acc;

    // ---- barrier 2: WAIT + combine ----
    if (t == 0) {
        while (atomicAdd(&g_cnt2[b], 0) < CPB) __nanosleep(32);
        __threadfence();
    }
    __syncthreads();
    if (t < 32) {
        const float pm = (t < CPB) ? *(volatile float*)&g_pm2[b * CPB + t] : -1e30f;
        const float pz = (t < CPB) ? *(volatile float*)&g_pz2[b * CPB + t] : 0.0f;
        const float ps = (t < CPB) ? *(volatile float*)&g_ps2[b * CPB + t] : 0.0f;
        const float M  = warpMax(pm);
        const float e  = __expf(pm - M);
        const float Z  = warpSum(pz * e);
        const float S  = warpSum(ps * e);
        if (t == 0) { sbc[0] = M; sbc[1] = 1.0f / Z; sbc[2] = S / Z; }
    }
    __syncthreads();
    const float scale = __expf(m2 - sbc[0]) * sbc[1];   // e^{m2-M2}/Z2
    const float sval  = sbc[2];                          // s_b

    if (t < 32) {
        float4 ssum = racc[t];
#pragma unroll
        for (int w2 = 1; w2 < 8; w2++) {
            const float4 u = racc[w2 * 32 + t];
            ssum.x += u.x; ssum.y += u.y; ssum.z += u.z; ssum.w += u.w;
        }
        ssum.x *= scale; ssum.y *= scale; ssum.z *= scale; ssum.w *= scale;
        reinterpret_cast<float4*>(g_rop + (size_t)bi * MEM_D)[t] = ssum;
    }
    __syncthreads();                          // rop stores issued
    if (t == 0) {
        __threadfence();
        atomicAdd(&g_cnt3[b], 1);
    }

    // ================= Epilogue: ch==0 block finishes the batch =================
    if (ch != 0) return;
    if (t == 0) {
        while (atomicAdd(&g_cnt3[b], 0) < CPB) __nanosleep(32);
        __threadfence();
    }
    __syncthreads();

    // sr (reuse sd1) = sum_ch rop + s * v
    if (t < MEM_D) {
        float accr = sval * sv[t];
        const float* rp = g_rop + (size_t)b * CPB * MEM_D + t;
#pragma unroll
        for (int c = 0; c < CPB; c++) accr += __ldcg(rp + c * MEM_D);
        sd1[t] = accr;
    }
    if (t == 0) {                             // reset counters for next replay
        g_cnt0[b] = 0; g_cnt1[b] = 0; g_cnt2[b] = 0; g_cnt3[b] = 0;
    }
    __syncthreads();

    // out[b, t] = bro[t] + sum_d sr[d] * Wro[d*IN_D + t]   (256 threads)
    {
        float a0 = 0.f, a1 = 0.f;
#pragma unroll 8
        for (int d = 0; d < MEM_D; d += 2) {
            a0 = fmaf(sd1[d],     Wro[(d)     * IN_D + t], a0);
            a1 = fmaf(sd1[d + 1], Wro[(d + 1) * IN_D + t], a1);
        }
        out[b * IN_D + t] = a0 + a1 + bro[t];
    }
}

// ---------------------------------------------------------------------------
extern "C" void kernel_launch(void* const* d_in, const int* in_sizes, int n_in,
                              void* d_out, int out_size) {
    const float* x   = (const float*)d_in[0];
    const float* mem = (const float*)d_in[1];
    const float* Ww  = (const float*)d_in[2];
    const float* bw  = (const float*)d_in[3];
    const float* Wq  = (const float*)d_in[4];
    const float* bq  = (const float*)d_in[5];
    const float* Wr  = (const float*)d_in[6];
    const float* br  = (const float*)d_in[7];
    const float* Wro = (const float*)d_in[8];
    const float* bro = (const float*)d_in[9];
    float* out = (float*)d_out;

    mega_kernel<<<BATCH * CPB, 256>>>(mem, x, Ww, bw, Wq, bq, Wr, br,
                                      Wro, bro, out);
}

// round 13
// speedup vs baseline: 1.0417x; 1.0371x over previous
#include <cuda_runtime.h>
#include <math.h>

// Problem constants
#define BATCH   64
#define IN_D    256
#define MEM_D   128
#define NSLOT   4096
#define CPB     8                  // chunks (blocks) per batch -> single wave
#define CHUNK   (NSLOT / CPB)      // 512 rows per block
#define KQ      8                  // K slices in proj (32 each)

// -------- scratch (no device allocations allowed) --------
__device__ float g_pp[3 * BATCH * KQ * MEM_D]; // proj partials [m][b][kq][o]
__device__ float g_v [BATCH * MEM_D];          // finalized v (written by fused ch==0)
__device__ float g_s [BATCH];
__device__ float g_rop[BATCH * CPB * MEM_D];   // per-chunk read_out partials

__device__ float g_pm1[BATCH * CPB];
__device__ float g_pz1[BATCH * CPB];
__device__ float g_pm2[BATCH * CPB];
__device__ float g_pz2[BATCH * CPB];
__device__ float g_ps2[BATCH * CPB];
__device__ int   g_cnt1[BATCH];                // zero-init; reset by out_kernel
__device__ int   g_cnt2[BATCH];

__device__ __forceinline__ float warpSum(float v) {
#pragma unroll
    for (int o = 16; o; o >>= 1) v += __shfl_xor_sync(0xffffffffu, v, o);
    return v;
}
__device__ __forceinline__ float warpMax(float v) {
#pragma unroll
    for (int o = 16; o; o >>= 1) v = fmaxf(v, __shfl_xor_sync(0xffffffffu, v, o));
    return v;
}
// block reduce for 256 threads (8 warps)
__device__ __forceinline__ float blockSum(float v, float* sred) {
    v = warpSum(v);
    if ((threadIdx.x & 31) == 0) sred[threadIdx.x >> 5] = v;
    __syncthreads();
    float r = sred[0];
#pragma unroll
    for (int i = 1; i < 8; i++) r += sred[i];
    __syncthreads();
    return r;
}
__device__ __forceinline__ float blockMax(float v, float* sred) {
    v = warpMax(v);
    if ((threadIdx.x & 31) == 0) sred[threadIdx.x >> 5] = v;
    __syncthreads();
    float r = sred[0];
#pragma unroll
    for (int i = 1; i < 8; i++) r = fmaxf(r, sred[i]);
    __syncthreads();
    return r;
}

// ---------------------------------------------------------------------------
// Kernel 1: projection PARTIALS. grid = 1536 (3 x 64 x 8 K-slices), blk 128.
// 32-load chains, 4 independent accumulators.
// ---------------------------------------------------------------------------
__global__ void __launch_bounds__(128)
proj_kernel(const float* __restrict__ x,
            const float* __restrict__ Ww,
            const float* __restrict__ Wq,
            const float* __restrict__ Wr) {
    const int m   = blockIdx.x >> 9;          // 0..2
    const int rem = blockIdx.x & 511;
    const int b   = rem >> 3;                 // 0..63
    const int kq  = rem & 7;                  // K slice
    const int t   = threadIdx.x;              // 0..127 (output column)

    const float* W = (m == 0) ? Ww : ((m == 1) ? Wq : Wr);
    const int k0 = kq * 32;

    __shared__ float sx[32];
    if (t < 32) sx[t] = x[b * IN_D + k0 + t];
    __syncthreads();

    float a0 = 0.f, a1 = 0.f, a2 = 0.f, a3 = 0.f;
    const float* Wc = W + (size_t)k0 * MEM_D + t;
#pragma unroll
    for (int k = 0; k < 32; k += 4) {
        a0 = fmaf(sx[k + 0], Wc[(k + 0) * MEM_D], a0);
        a1 = fmaf(sx[k + 1], Wc[(k + 1) * MEM_D], a1);
        a2 = fmaf(sx[k + 2], Wc[(k + 2) * MEM_D], a2);
        a3 = fmaf(sx[k + 3], Wc[(k + 3) * MEM_D], a3);
    }
    g_pp[(((m * BATCH) + b) * KQ + kq) * MEM_D + t] = (a0 + a1) + (a2 + a3);
}

// ---------------------------------------------------------------------------
// Kernel 2: FUSED dots + dual-softmax + accumulation, SINGLE WAVE.
// grid = 512 (64 x 8 chunks), block 256, 4 blocks/SM -> all resident.
// Phase 1 is SHUFFLE-FREE: per-thread 16-col partial dots go to smem
// (sp1/sp2[row*8+s], conflict-free), reduced afterwards -> load loop is pure
// LDG->FMA->STS with no cross-lane dependency, maximizing MLP.
// Phase 2 re-reads dense in REVERSE order with __ldcs (L2-hot).
// Barrier 2: arrive before phase 2, wait after (overlap).
// ---------------------------------------------------------------------------
__global__ void __launch_bounds__(256, 4)
fused_kernel(const float* __restrict__ mem,
             const float* __restrict__ bw,
             const float* __restrict__ bq,
             const float* __restrict__ br) {
    const int b  = blockIdx.x >> 3;
    const int ch = blockIdx.x & 7;
    const int bi = blockIdx.x;
    const int t  = threadIdx.x;
    const int lane = t & 31, w = t >> 5;      // 8 warps
    const int s = lane & 7, rsub = lane >> 3; // quarter-warp layout

    // 32KB pool: phase-1 partials; racc overlays it after phase 1 is reduced
    __shared__ __align__(16) char pool[32768];
    float*  sp1  = (float*)pool;                     // CHUNK*8 floats
    float*  sp2  = sp1 + CHUNK * 8;                  // CHUNK*8 floats
    float4* racc = (float4*)pool;                    // 256 float4 (overlay)

    __shared__ float sd1[CHUNK];              // d1 -> ww -> c'
    __shared__ float sd2[CHUNK];              // d2 -> rl
    __shared__ float swq[MEM_D];
    __shared__ float srq[MEM_D];
    __shared__ float sv [MEM_D];
    __shared__ float sred[8];
    __shared__ float sbc[2];

    if (t < MEM_D) {
        const float* pv = g_pp + ((0 * BATCH + b) * KQ) * MEM_D + t;
        const float* pq = g_pp + ((1 * BATCH + b) * KQ) * MEM_D + t;
        const float* pr = g_pp + ((2 * BATCH + b) * KQ) * MEM_D + t;
        float av = bw[t], aq = bq[t], ar = br[t];
#pragma unroll
        for (int j = 0; j < KQ; j++) {
            av += pv[j * MEM_D];
            aq += pq[j * MEM_D];
            ar += pr[j * MEM_D];
        }
        sv[t] = av; swq[t] = aq; srq[t] = ar;
        if (ch == 0) g_v[b * MEM_D + t] = av;     // publish for out_kernel
    }
    __syncthreads();

    // per-thread query slices (cols (j*8+s)*4 .. +3)
    float4 q4[4], r4[4];
#pragma unroll
    for (int j = 0; j < 4; j++) {
        q4[j] = reinterpret_cast<const float4*>(swq)[j * 8 + s];
        r4[j] = reinterpret_cast<const float4*>(srq)[j * 8 + s];
    }

    const float4* mb = reinterpret_cast<const float4*>(mem) +
                       ((size_t)b * NSLOT + (size_t)ch * CHUNK) * 32;

    // ======= Phase 1: shuffle-free coalesced dots (partials to smem) =======
#pragma unroll 4
    for (int it = 0; it < 16; it++) {
        const int r0 = it * 32 + w * 4 + rsub;
        const float4* grow = mb + (size_t)r0 * 32;
        const float4 v0 = grow[0 * 8 + s];
        const float4 v1 = grow[1 * 8 + s];
        const float4 v2 = grow[2 * 8 + s];
        const float4 v3 = grow[3 * 8 + s];
        float a, c;
        a  = v0.x * q4[0].x + v0.y * q4[0].y + v0.z * q4[0].z + v0.w * q4[0].w;
        a += v1.x * q4[1].x + v1.y * q4[1].y + v1.z * q4[1].z + v1.w * q4[1].w;
        a += v2.x * q4[2].x + v2.y * q4[2].y + v2.z * q4[2].z + v2.w * q4[2].w;
        a += v3.x * q4[3].x + v3.y * q4[3].y + v3.z * q4[3].z + v3.w * q4[3].w;
        c  = v0.x * r4[0].x + v0.y * r4[0].y + v0.z * r4[0].z + v0.w * r4[0].w;
        c += v1.x * r4[1].x + v1.y * r4[1].y + v1.z * r4[1].z + v1.w * r4[1].w;
        c += v2.x * r4[2].x + v2.y * r4[2].y + v2.z * r4[2].z + v2.w * r4[2].w;
        c += v3.x * r4[3].x + v3.y * r4[3].y + v3.z * r4[3].z + v3.w * r4[3].w;
        sp1[r0 * 8 + s] = a;                  // conflict-free STS
        sp2[r0 * 8 + s] = c;
    }
    __syncthreads();                          // sp1/sp2 complete

    // reduce 8 partials per row -> sd1/sd2 (2 rows per thread)
#pragma unroll
    for (int i = 0; i < 2; i++) {
        const int r = t + i * 256;
        const float4 p0 = reinterpret_cast<const float4*>(sp1)[r * 2];
        const float4 p1 = reinterpret_cast<const float4*>(sp1)[r * 2 + 1];
        sd1[r] = ((p0.x + p0.y) + (p0.z + p0.w)) +
                 ((p1.x + p1.y) + (p1.z + p1.w));
        const float4 u0 = reinterpret_cast<const float4*>(sp2)[r * 2];
        const float4 u1 = reinterpret_cast<const float4*>(sp2)[r * 2 + 1];
        sd2[r] = ((u0.x + u0.y) + (u0.z + u0.w)) +
                 ((u1.x + u1.y) + (u1.z + u1.w));
    }

    // qv = v . rq  (blockSum's internal syncs also publish sd1/sd2, free pool)
    float qp = (t < MEM_D) ? sv[t] * srq[t] : 0.0f;
    __syncthreads();
    const float qv = blockSum(qp, sred);

    // ---- local write-softmax partials (2 elems per thread) ----
    const float m1 = blockMax(fmaxf(sd1[t], sd1[t + 256]), sred);
    const float z1 = blockSum(__expf(sd1[t] - m1) + __expf(sd1[t + 256] - m1),
                              sred);

    // ---- barrier 1: full wait (ww needs global M1/Z1) ----
    if (t == 0) {
        *(volatile float*)&g_pm1[bi] = m1;
        *(volatile float*)&g_pz1[bi] = z1;
        __threadfence();
        atomicAdd(&g_cnt1[b], 1);
        while (atomicAdd(&g_cnt1[b], 0) < CPB) __nanosleep(32);
        __threadfence();
    }
    __syncthreads();
    if (t < 32) {
        const float pm = (t < CPB) ? *(volatile float*)&g_pm1[b * CPB + t] : -1e30f;
        const float pz = (t < CPB) ? *(volatile float*)&g_pz1[b * CPB + t] : 0.0f;
        const float M  = warpMax(pm);
        const float Z  = warpSum(pz * __expf(pm - M));
        if (t == 0) { sbc[0] = M; sbc[1] = 1.0f / Z; }
    }
    __syncthreads();
    const float M1 = sbc[0], invZ1 = sbc[1];

    // ---- ww (exact), read-logits; local read-softmax partials ----
    float m2l = -1e30f;
#pragma unroll
    for (int i = 0; i < 2; i++) {
        const int n = t + i * 256;
        const float ww = __expf(sd1[n] - M1) * invZ1;
        const float d2v = sd2[n];
        const float rl = d2v - ww * (d2v - qv);
        sd1[n] = ww;
        sd2[n] = rl;
        m2l = fmaxf(m2l, rl);
    }
    const float m2 = blockMax(m2l, sred);
    float lz2 = 0.0f, ls2 = 0.0f;
#pragma unroll
    for (int i = 0; i < 2; i++) {
        const int n = t + i * 256;
        const float e = __expf(sd2[n] - m2);
        lz2 += e;
        ls2 += e * sd1[n];
    }
    const float z2 = blockSum(lz2, sred);
    const float s2 = blockSum(ls2, sred);

    // ---- barrier 2: ARRIVE ONLY (wait deferred past phase 2) ----
    if (t == 0) {
        *(volatile float*)&g_pm2[bi] = m2;
        *(volatile float*)&g_pz2[bi] = z2;
        *(volatile float*)&g_ps2[bi] = s2;
        __threadfence();
        atomicAdd(&g_cnt2[b], 1);
    }

    // ---- c'_n = e^{rl_n - m2_loc} * (1 - ww_n)  (locally-scaled coeff) ----
#pragma unroll
    for (int i = 0; i < 2; i++) {
        const int n = t + i * 256;
        sd1[n] = __expf(sd2[n] - m2) * (1.0f - sd1[n]);
    }
    __syncthreads();

    // ---- Phase 2: dense weighted re-read, REVERSE order + streaming loads ----
    float4 acc[4];
#pragma unroll
    for (int j = 0; j < 4; j++) acc[j] = make_float4(0.f, 0.f, 0.f, 0.f);
#pragma unroll 2
    for (int it = 15; it >= 0; it--) {
        const int r0 = it * 32 + w * 4 + rsub;
        const float cv = sd1[r0];
        const float4* grow = mb + (size_t)r0 * 32;
#pragma unroll
        for (int j = 0; j < 4; j++) {
            const float4 m = __ldcs(grow + j * 8 + s);
            acc[j].x = fmaf(cv, m.x, acc[j].x);
            acc[j].y = fmaf(cv, m.y, acc[j].y);
            acc[j].z = fmaf(cv, m.z, acc[j].z);
            acc[j].w = fmaf(cv, m.w, acc[j].w);
        }
    }

    // ---- barrier 2: WAIT + combine (overlapped with peers' phase 2) ----
    if (t == 0) {
        while (atomicAdd(&g_cnt2[b], 0) < CPB) __nanosleep(32);
        __threadfence();
    }
    __syncthreads();
    if (t < 32) {
        const float pm = (t < CPB) ? *(volatile float*)&g_pm2[b * CPB + t] : -1e30f;
        const float pz = (t < CPB) ? *(volatile float*)&g_pz2[b * CPB + t] : 0.0f;
        const float ps = (t < CPB) ? *(volatile float*)&g_ps2[b * CPB + t] : 0.0f;
        const float M  = warpMax(pm);
        const float e  = __expf(pm - M);
        const float Z  = warpSum(pz * e);
        const float S  = warpSum(ps * e);
        if (t == 0) {
            sbc[0] = M; sbc[1] = 1.0f / Z;
            if (ch == 0) g_s[b] = S / Z;
        }
    }
    __syncthreads();
    const float scale = __expf(m2 - sbc[0]) * sbc[1];   // e^{m2-M2}/Z2

    // reduce across the 4 row-subgroups (lanes xor 8, 16), scale, store
#pragma unroll
    for (int o = 8; o <= 16; o <<= 1) {
#pragma unroll
        for (int j = 0; j < 4; j++) {
            acc[j].x += __shfl_xor_sync(0xffffffffu, acc[j].x, o);
            acc[j].y += __shfl_xor_sync(0xffffffffu, acc[j].y, o);
            acc[j].z += __shfl_xor_sync(0xffffffffu, acc[j].z, o);
            acc[j].w += __shfl_xor_sync(0xffffffffu, acc[j].w, o);
        }
    }
    if (rsub == 0) {
#pragma unroll
        for (int j = 0; j < 4; j++) {
            acc[j].x *= scale; acc[j].y *= scale;
            acc[j].z *= scale; acc[j].w *= scale;
            racc[w * 32 + j * 8 + s] = acc[j];
        }
    }
    __syncthreads();
    if (t < 32) {
        float4 ssum = racc[t];
#pragma unroll
        for (int w2 = 1; w2 < 8; w2++) {
            const float4 u = racc[w2 * 32 + t];
            ssum.x += u.x; ssum.y += u.y; ssum.z += u.z; ssum.w += u.w;
        }
        reinterpret_cast<float4*>(g_rop + (size_t)bi * MEM_D)[t] = ssum;
    }
}

// ---------------------------------------------------------------------------
// Kernel 3: sum chunk partials, add s*v, final projection; reset counters.
// grid 64, block 512 (2 threads per output, K halves).
// ---------------------------------------------------------------------------
__global__ void __launch_bounds__(512)
out_kernel(const float* __restrict__ Wro,
           const float* __restrict__ bro,
           float* __restrict__ out) {
    const int b = blockIdx.x;
    const int t = threadIdx.x;               // 0..511
    __shared__ float sr[MEM_D];
    __shared__ float so[512];
    if (t < MEM_D) {
        float acc = g_s[b] * g_v[b * MEM_D + t];
#pragma unroll
        for (int c = 0; c < CPB; c++)
            acc += g_rop[((size_t)b * CPB + c) * MEM_D + t];
        sr[t] = acc;
    }
    if (t == 0) { g_cnt1[b] = 0; g_cnt2[b] = 0; }   // reset for next replay
    __syncthreads();

    const int o = t & 255;
    const int h = t >> 8;
    float acc = 0.0f;
    const int d0 = h * 64;
#pragma unroll 8
    for (int d = 0; d < 64; d++)
        acc = fmaf(sr[d0 + d], Wro[(d0 + d) * IN_D + o], acc);
    so[t] = acc;
    __syncthreads();
    if (t < IN_D)
        out[b * IN_D + t] = so[t] + so[256 + t] + bro[t];
}

// ---------------------------------------------------------------------------
extern "C" void kernel_launch(void* const* d_in, const int* in_sizes, int n_in,
                              void* d_out, int out_size) {
    const float* x   = (const float*)d_in[0];
    const float* mem = (const float*)d_in[1];
    const float* Ww  = (const float*)d_in[2];
    const float* bw  = (const float*)d_in[3];
    const float* Wq  = (const float*)d_in[4];
    const float* bq  = (const float*)d_in[5];
    const float* Wr  = (const float*)d_in[6];
    const float* br  = (const float*)d_in[7];
    const float* Wro = (const float*)d_in[8];
    const float* bro = (const float*)d_in[9];
    float* out = (float*)d_out;

    proj_kernel<<<3 * BATCH * KQ, 128>>>(x, Ww, Wq, Wr);
    fused_kernel<<<BATCH * CPB, 256>>>(mem, bw, bq, br);
    out_kernel<<<BATCH, 512>>>(Wro, bro, out);
}

// round 14
// speedup vs baseline: 1.0929x; 1.0492x over previous
#include <cuda_runtime.h>
#include <math.h>

// Problem constants
#define BATCH   64
#define IN_D    256
#define MEM_D   128
#define NSLOT   4096
#define CPB     8                  // chunks (blocks) per batch -> single wave
#define CHUNK   (NSLOT / CPB)      // 512 rows per block
#define KQ      8                  // K slices in proj (32 each)

// -------- scratch (no device allocations allowed) --------
__device__ float g_pp[3 * BATCH * KQ * MEM_D]; // proj partials [m][b][kq][o]
__device__ float g_rop[BATCH * CPB * MEM_D];   // per-chunk read_out partials

__device__ float g_pm1[BATCH * CPB];
__device__ float g_pz1[BATCH * CPB];
__device__ float g_pm2[BATCH * CPB];
__device__ float g_pz2[BATCH * CPB];
__device__ float g_ps2[BATCH * CPB];
__device__ int   g_cnt1[BATCH];                // zero-init; reset by epilogue
__device__ int   g_cnt2[BATCH];
__device__ int   g_cnt3[BATCH];

__device__ __forceinline__ float warpSum(float v) {
#pragma unroll
    for (int o = 16; o; o >>= 1) v += __shfl_xor_sync(0xffffffffu, v, o);
    return v;
}
__device__ __forceinline__ float warpMax(float v) {
#pragma unroll
    for (int o = 16; o; o >>= 1) v = fmaxf(v, __shfl_xor_sync(0xffffffffu, v, o));
    return v;
}
// block reduce for 256 threads (8 warps)
__device__ __forceinline__ float blockSum(float v, float* sred) {
    v = warpSum(v);
    if ((threadIdx.x & 31) == 0) sred[threadIdx.x >> 5] = v;
    __syncthreads();
    float r = sred[0];
#pragma unroll
    for (int i = 1; i < 8; i++) r += sred[i];
    __syncthreads();
    return r;
}
__device__ __forceinline__ float blockMax(float v, float* sred) {
    v = warpMax(v);
    if ((threadIdx.x & 31) == 0) sred[threadIdx.x >> 5] = v;
    __syncthreads();
    float r = sred[0];
#pragma unroll
    for (int i = 1; i < 8; i++) r = fmaxf(r, sred[i]);
    __syncthreads();
    return r;
}

// ---------------------------------------------------------------------------
// Kernel 1: projection PARTIALS. grid = 1536 (3 x 64 x 8 K-slices), blk 128.
// No smem, no sync: x read via uniform broadcast loads, interleaved with
// coalesced W loads -> all 64 loads independent, single latency trip.
// ---------------------------------------------------------------------------
__global__ void __launch_bounds__(128)
proj_kernel(const float* __restrict__ x,
            const float* __restrict__ Ww,
            const float* __restrict__ Wq,
            const float* __restrict__ Wr) {
    const int m   = blockIdx.x >> 9;          // 0..2
    const int rem = blockIdx.x & 511;
    const int b   = rem >> 3;                 // 0..63
    const int kq  = rem & 7;                  // K slice
    const int t   = threadIdx.x;              // 0..127 (output column)

    const float* W = (m == 0) ? Ww : ((m == 1) ? Wq : Wr);
    const int k0 = kq * 32;
    const float* xb = x + b * IN_D + k0;      // uniform across block
    const float* Wc = W + (size_t)k0 * MEM_D + t;

    float a0 = 0.f, a1 = 0.f, a2 = 0.f, a3 = 0.f;
#pragma unroll
    for (int k = 0; k < 32; k += 4) {
        const float x0 = __ldg(xb + k + 0);
        const float x1 = __ldg(xb + k + 1);
        const float x2 = __ldg(xb + k + 2);
        const float x3 = __ldg(xb + k + 3);
        a0 = fmaf(x0, Wc[(k + 0) * MEM_D], a0);
        a1 = fmaf(x1, Wc[(k + 1) * MEM_D], a1);
        a2 = fmaf(x2, Wc[(k + 2) * MEM_D], a2);
        a3 = fmaf(x3, Wc[(k + 3) * MEM_D], a3);
    }
    g_pp[(((m * BATCH) + b) * KQ + kq) * MEM_D + t] = (a0 + a1) + (a2 + a3);
}

// ---------------------------------------------------------------------------
// Kernel 2: FUSED dots + dual-softmax + accumulation + OUTPUT, SINGLE WAVE.
// grid = 512 (64 x 8 chunks), block 256, 4 blocks/SM -> all resident.
// Phase 1: shuffle-free coalesced dots (partials to smem, reduced after).
// Phase 2: dense weighted re-read, reverse order, __ldcs (L2-hot).
// Barrier 2 split (arrive before phase 2, wait after).
// Epilogue: ch==0 block sums rop partials + s*v, projects through W_ro,
// writes out, and resets counters (all siblings provably done).
// ---------------------------------------------------------------------------
__global__ void __launch_bounds__(256, 4)
fused_kernel(const float* __restrict__ mem,
             const float* __restrict__ bw,
             const float* __restrict__ bq,
             const float* __restrict__ br,
             const float* __restrict__ Wro,
             const float* __restrict__ bro,
             float* __restrict__ out) {
    const int b  = blockIdx.x >> 3;
    const int ch = blockIdx.x & 7;
    const int bi = blockIdx.x;
    const int t  = threadIdx.x;
    const int lane = t & 31, w = t >> 5;      // 8 warps
    const int s = lane & 7, rsub = lane >> 3; // quarter-warp layout

    // 32KB pool: phase-1 partials; racc overlays it after phase 1 is reduced
    __shared__ __align__(16) char pool[32768];
    float*  sp1  = (float*)pool;                     // CHUNK*8 floats
    float*  sp2  = sp1 + CHUNK * 8;                  // CHUNK*8 floats
    float4* racc = (float4*)pool;                    // 256 float4 (overlay)

    __shared__ float sd1[CHUNK];              // d1 -> ww -> c'
    __shared__ float sd2[CHUNK];              // d2 -> rl
    __shared__ float swq[MEM_D];
    __shared__ float srq[MEM_D];              // later reused as sr (epilogue)
    __shared__ float sv [MEM_D];
    __shared__ float sred[8];
    __shared__ float sbc[3];

    if (t < MEM_D) {
        const float* pv = g_pp + ((0 * BATCH + b) * KQ) * MEM_D + t;
        const float* pq = g_pp + ((1 * BATCH + b) * KQ) * MEM_D + t;
        const float* pr = g_pp + ((2 * BATCH + b) * KQ) * MEM_D + t;
        float av = bw[t], aq = bq[t], ar = br[t];
#pragma unroll
        for (int j = 0; j < KQ; j++) {
            av += pv[j * MEM_D];
            aq += pq[j * MEM_D];
            ar += pr[j * MEM_D];
        }
        sv[t] = av; swq[t] = aq; srq[t] = ar;
    }
    __syncthreads();

    // per-thread query slices (cols (j*8+s)*4 .. +3)
    float4 q4[4], r4[4];
#pragma unroll
    for (int j = 0; j < 4; j++) {
        q4[j] = reinterpret_cast<const float4*>(swq)[j * 8 + s];
        r4[j] = reinterpret_cast<const float4*>(srq)[j * 8 + s];
    }

    const float4* mb = reinterpret_cast<const float4*>(mem) +
                       ((size_t)b * NSLOT + (size_t)ch * CHUNK) * 32;

    // ======= Phase 1: shuffle-free coalesced dots (partials to smem) =======
#pragma unroll 4
    for (int it = 0; it < 16; it++) {
        const int r0 = it * 32 + w * 4 + rsub;
        const float4* grow = mb + (size_t)r0 * 32;
        const float4 v0 = grow[0 * 8 + s];
        const float4 v1 = grow[1 * 8 + s];
        const float4 v2 = grow[2 * 8 + s];
        const float4 v3 = grow[3 * 8 + s];
        float a, c;
        a  = v0.x * q4[0].x + v0.y * q4[0].y + v0.z * q4[0].z + v0.w * q4[0].w;
        a += v1.x * q4[1].x + v1.y * q4[1].y + v1.z * q4[1].z + v1.w * q4[1].w;
        a += v2.x * q4[2].x + v2.y * q4[2].y + v2.z * q4[2].z + v2.w * q4[2].w;
        a += v3.x * q4[3].x + v3.y * q4[3].y + v3.z * q4[3].z + v3.w * q4[3].w;
        c  = v0.x * r4[0].x + v0.y * r4[0].y + v0.z * r4[0].z + v0.w * r4[0].w;
        c += v1.x * r4[1].x + v1.y * r4[1].y + v1.z * r4[1].z + v1.w * r4[1].w;
        c += v2.x * r4[2].x + v2.y * r4[2].y + v2.z * r4[2].z + v2.w * r4[2].w;
        c += v3.x * r4[3].x + v3.y * r4[3].y + v3.z * r4[3].z + v3.w * r4[3].w;
        sp1[r0 * 8 + s] = a;                  // conflict-free STS
        sp2[r0 * 8 + s] = c;
    }
    __syncthreads();                          // sp1/sp2 complete

    // reduce 8 partials per row -> sd1/sd2 (2 rows per thread)
#pragma unroll
    for (int i = 0; i < 2; i++) {
        const int r = t + i * 256;
        const float4 p0 = reinterpret_cast<const float4*>(sp1)[r * 2];
        const float4 p1 = reinterpret_cast<const float4*>(sp1)[r * 2 + 1];
        sd1[r] = ((p0.x + p0.y) + (p0.z + p0.w)) +
                 ((p1.x + p1.y) + (p1.z + p1.w));
        const float4 u0 = reinterpret_cast<const float4*>(sp2)[r * 2];
        const float4 u1 = reinterpret_cast<const float4*>(sp2)[r * 2 + 1];
        sd2[r] = ((u0.x + u0.y) + (u0.z + u0.w)) +
                 ((u1.x + u1.y) + (u1.z + u1.w));
    }

    // qv = v . rq  (blockSum's internal syncs also publish sd1/sd2, free pool)
    float qp = (t < MEM_D) ? sv[t] * srq[t] : 0.0f;
    __syncthreads();
    const float qv = blockSum(qp, sred);

    // ---- local write-softmax partials (2 elems per thread) ----
    const float m1 = blockMax(fmaxf(sd1[t], sd1[t + 256]), sred);
    const float z1 = blockSum(__expf(sd1[t] - m1) + __expf(sd1[t + 256] - m1),
                              sred);

    // ---- barrier 1: full wait (ww needs global M1/Z1) ----
    if (t == 0) {
        *(volatile float*)&g_pm1[bi] = m1;
        *(volatile float*)&g_pz1[bi] = z1;
        __threadfence();
        atomicAdd(&g_cnt1[b], 1);
        while (atomicAdd(&g_cnt1[b], 0) < CPB) __nanosleep(32);
        __threadfence();
    }
    __syncthreads();
    if (t < 32) {
        const float pm = (t < CPB) ? *(volatile float*)&g_pm1[b * CPB + t] : -1e30f;
        const float pz = (t < CPB) ? *(volatile float*)&g_pz1[b * CPB + t] : 0.0f;
        const float M  = warpMax(pm);
        const float Z  = warpSum(pz * __expf(pm - M));
        if (t == 0) { sbc[0] = M; sbc[1] = 1.0f / Z; }
    }
    __syncthreads();
    const float M1 = sbc[0], invZ1 = sbc[1];

    // ---- ww (exact), read-logits; local read-softmax partials ----
    float m2l = -1e30f;
#pragma unroll
    for (int i = 0; i < 2; i++) {
        const int n = t + i * 256;
        const float ww = __expf(sd1[n] - M1) * invZ1;
        const float d2v = sd2[n];
        const float rl = d2v - ww * (d2v - qv);
        sd1[n] = ww;
        sd2[n] = rl;
        m2l = fmaxf(m2l, rl);
    }
    const float m2 = blockMax(m2l, sred);
    float lz2 = 0.0f, ls2 = 0.0f;
#pragma unroll
    for (int i = 0; i < 2; i++) {
        const int n = t + i * 256;
        const float e = __expf(sd2[n] - m2);
        lz2 += e;
        ls2 += e * sd1[n];
    }
    const float z2 = blockSum(lz2, sred);
    const float s2 = blockSum(ls2, sred);

    // ---- barrier 2: ARRIVE ONLY (wait deferred past phase 2) ----
    if (t == 0) {
        *(volatile float*)&g_pm2[bi] = m2;
        *(volatile float*)&g_pz2[bi] = z2;
        *(volatile float*)&g_ps2[bi] = s2;
        __threadfence();
        atomicAdd(&g_cnt2[b], 1);
    }

    // ---- c'_n = e^{rl_n - m2_loc} * (1 - ww_n)  (locally-scaled coeff) ----
#pragma unroll
    for (int i = 0; i < 2; i++) {
        const int n = t + i * 256;
        sd1[n] = __expf(sd2[n] - m2) * (1.0f - sd1[n]);
    }
    __syncthreads();

    // ---- Phase 2: dense weighted re-read, REVERSE order + streaming loads ----
    float4 acc[4];
#pragma unroll
    for (int j = 0; j < 4; j++) acc[j] = make_float4(0.f, 0.f, 0.f, 0.f);
#pragma unroll 2
    for (int it = 15; it >= 0; it--) {
        const int r0 = it * 32 + w * 4 + rsub;
        const float cv = sd1[r0];
        const float4* grow = mb + (size_t)r0 * 32;
#pragma unroll
        for (int j = 0; j < 4; j++) {
            const float4 m = __ldcs(grow + j * 8 + s);
            acc[j].x = fmaf(cv, m.x, acc[j].x);
            acc[j].y = fmaf(cv, m.y, acc[j].y);
            acc[j].z = fmaf(cv, m.z, acc[j].z);
            acc[j].w = fmaf(cv, m.w, acc[j].w);
        }
    }

    // ---- barrier 2: WAIT + combine (overlapped with peers' phase 2) ----
    if (t == 0) {
        while (atomicAdd(&g_cnt2[b], 0) < CPB) __nanosleep(32);
        __threadfence();
    }
    __syncthreads();
    if (t < 32) {
        const float pm = (t < CPB) ? *(volatile float*)&g_pm2[b * CPB + t] : -1e30f;
        const float pz = (t < CPB) ? *(volatile float*)&g_pz2[b * CPB + t] : 0.0f;
        const float ps = (t < CPB) ? *(volatile float*)&g_ps2[b * CPB + t] : 0.0f;
        const float M  = warpMax(pm);
        const float e  = __expf(pm - M);
        const float Z  = warpSum(pz * e);
        const float S  = warpSum(ps * e);
        if (t == 0) { sbc[0] = M; sbc[1] = 1.0f / Z; sbc[2] = S / Z; }
    }
    __syncthreads();
    const float scale = __expf(m2 - sbc[0]) * sbc[1];   // e^{m2-M2}/Z2
    const float sval  = sbc[2];                          // s_b

    // reduce across the 4 row-subgroups (lanes xor 8, 16), scale, store
#pragma unroll
    for (int o = 8; o <= 16; o <<= 1) {
#pragma unroll
        for (int j = 0; j < 4; j++) {
            acc[j].x += __shfl_xor_sync(0xffffffffu, acc[j].x, o);
            acc[j].y += __shfl_xor_sync(0xffffffffu, acc[j].y, o);
            acc[j].z += __shfl_xor_sync(0xffffffffu, acc[j].z, o);
            acc[j].w += __shfl_xor_sync(0xffffffffu, acc[j].w, o);
        }
    }
    if (rsub == 0) {
#pragma unroll
        for (int j = 0; j < 4; j++) {
            acc[j].x *= scale; acc[j].y *= scale;
            acc[j].z *= scale; acc[j].w *= scale;
            racc[w * 32 + j * 8 + s] = acc[j];
        }
    }
    __syncthreads();
    if (t < 32) {
        float4 ssum = racc[t];
#pragma unroll
        for (int w2 = 1; w2 < 8; w2++) {
            const float4 u = racc[w2 * 32 + t];
            ssum.x += u.x; ssum.y += u.y; ssum.z += u.z; ssum.w += u.w;
        }
        reinterpret_cast<float4*>(g_rop + (size_t)bi * MEM_D)[t] = ssum;
    }
    __syncthreads();                          // rop stores issued
    if (t == 0) {
        __threadfence();
        atomicAdd(&g_cnt3[b], 1);
    }

    // ============ Epilogue: ch==0 block finishes the batch ============
    if (ch != 0) return;
    if (t == 0) {
        while (atomicAdd(&g_cnt3[b], 0) < CPB) __nanosleep(32);
        __threadfence();
    }
    __syncthreads();

    // sr (reuse srq) = sum_ch rop + s * v
    if (t < MEM_D) {
        float accr = sval * sv[t];
        const float* rp = g_rop + (size_t)b * CPB * MEM_D + t;
#pragma unroll
        for (int c = 0; c < CPB; c++) accr += __ldcg(rp + c * MEM_D);
        srq[t] = accr;
    }
    if (t == 0) {                             // reset counters for next replay
        g_cnt1[b] = 0; g_cnt2[b] = 0; g_cnt3[b] = 0;
    }
    __syncthreads();

    // out[b, t] = bro[t] + sum_d sr[d] * Wro[d*IN_D + t]   (256 threads)
    {
        float a0 = 0.f, a1 = 0.f;
#pragma unroll 8
        for (int d = 0; d < MEM_D; d += 2) {
            a0 = fmaf(srq[d],     Wro[(d)     * IN_D + t], a0);
            a1 = fmaf(srq[d + 1], Wro[(d + 1) * IN_D + t], a1);
        }
        out[b * IN_D + t] = a0 + a1 + bro[t];
    }
}

// ---------------------------------------------------------------------------
extern "C" void kernel_launch(void* const* d_in, const int* in_sizes, int n_in,
                              void* d_out, int out_size) {
    const float* x   = (const float*)d_in[0];
    const float* mem = (const float*)d_in[1];
    const float* Ww  = (const float*)d_in[2];
    const float* bw  = (const float*)d_in[3];
    const float* Wq  = (const float*)d_in[4];
    const float* bq  = (const float*)d_in[5];
    const float* Wr  = (const float*)d_in[6];
    const float* br  = (const float*)d_in[7];
    const float* Wro = (const float*)d_in[8];
    const float* bro = (const float*)d_in[9];
    float* out = (float*)d_out;

    proj_kernel<<<3 * BATCH * KQ, 128>>>(x, Ww, Wq, Wr);
    fused_kernel<<<BATCH * CPB, 256>>>(mem, bw, bq, br, Wro, bro, out);
}

// round 15
// speedup vs baseline: 1.1905x; 1.0893x over previous
#include <cuda_runtime.h>
#include <math.h>

// Problem constants
#define BATCH   64
#define IN_D    256
#define MEM_D   128
#define NSLOT   4096
#define CPB     8                  // chunks (blocks) per batch -> single wave
#define CHUNK   (NSLOT / CPB)      // 512 rows per block
#define KQ      8                  // K slices in proj (32 each)
#define TROWS   32                 // rows per cp.async tile
#define NTILE   (CHUNK / TROWS)    // 16 tiles

// -------- scratch (no device allocations allowed) --------
__device__ float g_pp[3 * BATCH * KQ * MEM_D]; // proj partials [m][b][kq][o]
__device__ float g_rop[BATCH * CPB * MEM_D];   // per-chunk read_out partials

__device__ float g_pm1[BATCH * CPB];
__device__ float g_pz1[BATCH * CPB];
__device__ float g_pm2[BATCH * CPB];
__device__ float g_pz2[BATCH * CPB];
__device__ float g_ps2[BATCH * CPB];
__device__ int   g_cnt1[BATCH];                // zero-init; reset by epilogue
__device__ int   g_cnt2[BATCH];
__device__ int   g_cnt3[BATCH];

__device__ __forceinline__ float warpSum(float v) {
#pragma unroll
    for (int o = 16; o; o >>= 1) v += __shfl_xor_sync(0xffffffffu, v, o);
    return v;
}
__device__ __forceinline__ float warpMax(float v) {
#pragma unroll
    for (int o = 16; o; o >>= 1) v = fmaxf(v, __shfl_xor_sync(0xffffffffu, v, o));
    return v;
}
// block reduce for 256 threads (8 warps)
__device__ __forceinline__ float blockSum(float v, float* sred) {
    v = warpSum(v);
    if ((threadIdx.x & 31) == 0) sred[threadIdx.x >> 5] = v;
    __syncthreads();
    float r = sred[0];
#pragma unroll
    for (int i = 1; i < 8; i++) r += sred[i];
    __syncthreads();
    return r;
}
__device__ __forceinline__ float blockMax(float v, float* sred) {
    v = warpMax(v);
    if ((threadIdx.x & 31) == 0) sred[threadIdx.x >> 5] = v;
    __syncthreads();
    float r = sred[0];
#pragma unroll
    for (int i = 1; i < 8; i++) r = fmaxf(r, sred[i]);
    __syncthreads();
    return r;
}

__device__ __forceinline__ void cp16(float4* dst_smem, const float4* src) {
    unsigned sa = (unsigned)__cvta_generic_to_shared(dst_smem);
    asm volatile("cp.async.cg.shared.global [%0], [%1], 16;\n"
                 :: "r"(sa), "l"(src) : "memory");
}

// ---------------------------------------------------------------------------
// Kernel 1: projection PARTIALS. grid = 1536 (3 x 64 x 8 K-slices), blk 128.
// No smem, no sync: x via uniform broadcast loads, W coalesced; all loads
// independent -> single latency trip.
// ---------------------------------------------------------------------------
__global__ void __launch_bounds__(128)
proj_kernel(const float* __restrict__ x,
            const float* __restrict__ Ww,
            const float* __restrict__ Wq,
            const float* __restrict__ Wr) {
    const int m   = blockIdx.x >> 9;          // 0..2
    const int rem = blockIdx.x & 511;
    const int b   = rem >> 3;                 // 0..63
    const int kq  = rem & 7;                  // K slice
    const int t   = threadIdx.x;              // 0..127 (output column)

    const float* W = (m == 0) ? Ww : ((m == 1) ? Wq : Wr);
    const int k0 = kq * 32;
    const float* xb = x + b * IN_D + k0;      // uniform across block
    const float* Wc = W + (size_t)k0 * MEM_D + t;

    float a0 = 0.f, a1 = 0.f, a2 = 0.f, a3 = 0.f;
#pragma unroll
    for (int k = 0; k < 32; k += 4) {
        const float x0 = __ldg(xb + k + 0);
        const float x1 = __ldg(xb + k + 1);
        const float x2 = __ldg(xb + k + 2);
        const float x3 = __ldg(xb + k + 3);
        a0 = fmaf(x0, Wc[(k + 0) * MEM_D], a0);
        a1 = fmaf(x1, Wc[(k + 1) * MEM_D], a1);
        a2 = fmaf(x2, Wc[(k + 2) * MEM_D], a2);
        a3 = fmaf(x3, Wc[(k + 3) * MEM_D], a3);
    }
    g_pp[(((m * BATCH) + b) * KQ + kq) * MEM_D + t] = (a0 + a1) + (a2 + a3);
}

// ---------------------------------------------------------------------------
// Kernel 2: FUSED dots + dual-softmax + accumulation + OUTPUT, SINGLE WAVE.
// grid = 512 (64 x 8 chunks), block 256, 4 blocks/SM -> all resident.
// Phase 1: cp.async double-buffered tile pipeline (16KB tiles). Each thread
// copies and then reads back EXACTLY its own slots -> per-thread wait_group
// suffices; no __syncthreads in the loop. Register-free load payload ->
// deep MLP regardless of register budget.
// Phase 2: dense weighted re-read, reverse order, __ldcs (L2-hot).
// Barrier 2 split (arrive before phase 2, wait after).
// Epilogue: ch==0 block reduces rop + s*v, projects through W_ro, resets cnts.
// ---------------------------------------------------------------------------
__global__ void __launch_bounds__(256, 4)
fused_kernel(const float* __restrict__ mem,
             const float* __restrict__ bw,
             const float* __restrict__ bq,
             const float* __restrict__ br,
             const float* __restrict__ Wro,
             const float* __restrict__ bro,
             float* __restrict__ out) {
    const int b  = blockIdx.x >> 3;
    const int ch = blockIdx.x & 7;
    const int bi = blockIdx.x;
    const int t  = threadIdx.x;
    const int lane = t & 31, w = t >> 5;      // 8 warps
    const int s = lane & 7, rsub = lane >> 3; // quarter-warp layout

    // 32KB pool: two 16KB cp.async tiles; racc overlays after phase 2 compute
    __shared__ __align__(16) char pool[32768];
    float4* tile0 = (float4*)pool;                   // 1024 float4
    float4* tile1 = tile0 + TROWS * 32;              // 1024 float4
    float4* racc  = (float4*)pool;                   // 256 float4 (overlay)

    __shared__ float sd1[CHUNK];              // d1 -> ww -> c'
    __shared__ float sd2[CHUNK];              // d2 -> rl
    __shared__ float swq[MEM_D];
    __shared__ float srq[MEM_D];              // later reused as sr (epilogue)
    __shared__ float sv [MEM_D];
    __shared__ float sred[8];
    __shared__ float sbc[3];

    if (t < MEM_D) {
        const float* pv = g_pp + ((0 * BATCH + b) * KQ) * MEM_D + t;
        const float* pq = g_pp + ((1 * BATCH + b) * KQ) * MEM_D + t;
        const float* pr = g_pp + ((2 * BATCH + b) * KQ) * MEM_D + t;
        float av = bw[t], aq = bq[t], ar = br[t];
#pragma unroll
        for (int j = 0; j < KQ; j++) {
            av += pv[j * MEM_D];
            aq += pq[j * MEM_D];
            ar += pr[j * MEM_D];
        }
        sv[t] = av; swq[t] = aq; srq[t] = ar;
    }
    __syncthreads();

    // per-thread query slices (cols (j*8+s)*4 .. +3)
    float4 q4[4], r4[4];
#pragma unroll
    for (int j = 0; j < 4; j++) {
        q4[j] = reinterpret_cast<const float4*>(swq)[j * 8 + s];
        r4[j] = reinterpret_cast<const float4*>(srq)[j * 8 + s];
    }

    const float4* mb = reinterpret_cast<const float4*>(mem) +
                       ((size_t)b * NSLOT + (size_t)ch * CHUNK) * 32;

    // ======= Phase 1: cp.async pipelined dots =======
    // Thread t owns tile slot (row = t>>3, s = t&7), j = 0..3. It copies its
    // own slots and reads back only those -> per-thread sync, no barriers.
    const int trow = t >> 3;                  // 0..31
    {
        // prologue: tiles 0 and 1 in flight
#pragma unroll
        for (int j = 0; j < 4; j++)
            cp16(tile0 + trow * 32 + j * 8 + s,
                 mb + (size_t)trow * 32 + j * 8 + s);
        asm volatile("cp.async.commit_group;" ::: "memory");
#pragma unroll
        for (int j = 0; j < 4; j++)
            cp16(tile1 + trow * 32 + j * 8 + s,
                 mb + (size_t)(TROWS + trow) * 32 + j * 8 + s);
        asm volatile("cp.async.commit_group;" ::: "memory");

        for (int it = 0; it < NTILE; it++) {
            float4* cur = (it & 1) ? tile1 : tile0;
            if (it < NTILE - 1) {
                asm volatile("cp.async.wait_group 1;" ::: "memory");
            } else {
                asm volatile("cp.async.wait_group 0;" ::: "memory");
            }
            // compute row it*TROWS + trow from own smem slots
            float a = 0.0f, c = 0.0f;
#pragma unroll
            for (int j = 0; j < 4; j++) {
                const float4 m = cur[trow * 32 + j * 8 + s];
                a = fmaf(m.x, q4[j].x, a); a = fmaf(m.y, q4[j].y, a);
                a = fmaf(m.z, q4[j].z, a); a = fmaf(m.w, q4[j].w, a);
                c = fmaf(m.x, r4[j].x, c); c = fmaf(m.y, r4[j].y, c);
                c = fmaf(m.z, r4[j].z, c); c = fmaf(m.w, r4[j].w, c);
            }
#pragma unroll
            for (int o = 4; o; o >>= 1) {     // reduce over s (8 lanes)
                a += __shfl_xor_sync(0xffffffffu, a, o);
                c += __shfl_xor_sync(0xffffffffu, c, o);
            }
            if (s == 0) {
                sd1[it * TROWS + trow] = a;
                sd2[it * TROWS + trow] = c;
            }
            // refill this buffer with tile it+2 (own slots only)
            if (it + 2 < NTILE) {
#pragma unroll
                for (int j = 0; j < 4; j++)
                    cp16(cur + trow * 32 + j * 8 + s,
                         mb + (size_t)((it + 2) * TROWS + trow) * 32 + j * 8 + s);
                asm volatile("cp.async.commit_group;" ::: "memory");
            }
        }
    }

    // qv = v . rq  (blockSum's internal syncs also publish sd1/sd2)
    float qp = (t < MEM_D) ? sv[t] * srq[t] : 0.0f;
    __syncthreads();
    const float qv = blockSum(qp, sred);

    // ---- local write-softmax partials (2 elems per thread) ----
    const float m1 = blockMax(fmaxf(sd1[t], sd1[t + 256]), sred);
    const float z1 = blockSum(__expf(sd1[t] - m1) + __expf(sd1[t + 256] - m1),
                              sred);

    // ---- barrier 1: full wait (ww needs global M1/Z1) ----
    if (t == 0) {
        *(volatile float*)&g_pm1[bi] = m1;
        *(volatile float*)&g_pz1[bi] = z1;
        __threadfence();
        atomicAdd(&g_cnt1[b], 1);
        while (atomicAdd(&g_cnt1[b], 0) < CPB) __nanosleep(32);
        __threadfence();
    }
    __syncthreads();
    if (t < 32) {
        const float pm = (t < CPB) ? *(volatile float*)&g_pm1[b * CPB + t] : -1e30f;
        const float pz = (t < CPB) ? *(volatile float*)&g_pz1[b * CPB + t] : 0.0f;
        const float M  = warpMax(pm);
        const float Z  = warpSum(pz * __expf(pm - M));
        if (t == 0) { sbc[0] = M; sbc[1] = 1.0f / Z; }
    }
    __syncthreads();
    const float M1 = sbc[0], invZ1 = sbc[1];

    // ---- ww (exact), read-logits; local read-softmax partials ----
    float m2l = -1e30f;
#pragma unroll
    for (int i = 0; i < 2; i++) {
        const int n = t + i * 256;
        const float ww = __expf(sd1[n] - M1) * invZ1;
        const float d2v = sd2[n];
        const float rl = d2v - ww * (d2v - qv);
        sd1[n] = ww;
        sd2[n] = rl;
        m2l = fmaxf(m2l, rl);
    }
    const float m2 = blockMax(m2l, sred);
    float lz2 = 0.0f, ls2 = 0.0f;
#pragma unroll
    for (int i = 0; i < 2; i++) {
        const int n = t + i * 256;
        const float e = __expf(sd2[n] - m2);
        lz2 += e;
        ls2 += e * sd1[n];
    }
    const float z2 = blockSum(lz2, sred);
    const float s2 = blockSum(ls2, sred);

    // ---- barrier 2: ARRIVE ONLY (wait deferred past phase 2) ----
    if (t == 0) {
        *(volatile float*)&g_pm2[bi] = m2;
        *(volatile float*)&g_pz2[bi] = z2;
        *(volatile float*)&g_ps2[bi] = s2;
        __threadfence();
        atomicAdd(&g_cnt2[b], 1);
    }

    // ---- c'_n = e^{rl_n - m2_loc} * (1 - ww_n)  (locally-scaled coeff) ----
#pragma unroll
    for (int i = 0; i < 2; i++) {
        const int n = t + i * 256;
        sd1[n] = __expf(sd2[n] - m2) * (1.0f - sd1[n]);
    }
    __syncthreads();

    // ---- Phase 2: dense weighted re-read, REVERSE order + streaming loads ----
    float4 acc[4];
#pragma unroll
    for (int j = 0; j < 4; j++) acc[j] = make_float4(0.f, 0.f, 0.f, 0.f);
#pragma unroll 2
    for (int it = 15; it >= 0; it--) {
        const int r0 = it * 32 + w * 4 + rsub;
        const float cv = sd1[r0];
        const float4* grow = mb + (size_t)r0 * 32;
#pragma unroll
        for (int j = 0; j < 4; j++) {
            const float4 m = __ldcs(grow + j * 8 + s);
            acc[j].x = fmaf(cv, m.x, acc[j].x);
            acc[j].y = fmaf(cv, m.y, acc[j].y);
            acc[j].z = fmaf(cv, m.z, acc[j].z);
            acc[j].w = fmaf(cv, m.w, acc[j].w);
        }
    }

    // ---- barrier 2: WAIT + combine (overlapped with peers' phase 2) ----
    if (t == 0) {
        while (atomicAdd(&g_cnt2[b], 0) < CPB) __nanosleep(32);
        __threadfence();
    }
    __syncthreads();
    if (t < 32) {
        const float pm = (t < CPB) ? *(volatile float*)&g_pm2[b * CPB + t] : -1e30f;
        const float pz = (t < CPB) ? *(volatile float*)&g_pz2[b * CPB + t] : 0.0f;
        const float ps = (t < CPB) ? *(volatile float*)&g_ps2[b * CPB + t] : 0.0f;
        const float M  = warpMax(pm);
        const float e  = __expf(pm - M);
        const float Z  = warpSum(pz * e);
        const float S  = warpSum(ps * e);
        if (t == 0) { sbc[0] = M; sbc[1] = 1.0f / Z; sbc[2] = S / Z; }
    }
    __syncthreads();
    const float scale = __expf(m2 - sbc[0]) * sbc[1];   // e^{m2-M2}/Z2
    const float sval  = sbc[2];                          // s_b

    // reduce across the 4 row-subgroups (lanes xor 8, 16), scale, store
#pragma unroll
    for (int o = 8; o <= 16; o <<= 1) {
#pragma unroll
        for (int j = 0; j < 4; j++) {
            acc[j].x += __shfl_xor_sync(0xffffffffu, acc[j].x, o);
            acc[j].y += __shfl_xor_sync(0xffffffffu, acc[j].y, o);
            acc[j].z += __shfl_xor_sync(0xffffffffu, acc[j].z, o);
            acc[j].w += __shfl_xor_sync(0xffffffffu, acc[j].w, o);
        }
    }
    if (rsub == 0) {
#pragma unroll
        for (int j = 0; j < 4; j++) {
            acc[j].x *= scale; acc[j].y *= scale;
            acc[j].z *= scale; acc[j].w *= scale;
            racc[w * 32 + j * 8 + s] = acc[j];
        }
    }
    __syncthreads();
    if (t < 32) {
        float4 ssum = racc[t];
#pragma unroll
        for (int w2 = 1; w2 < 8; w2++) {
            const float4 u = racc[w2 * 32 + t];
            ssum.x += u.x; ssum.y += u.y; ssum.z += u.z; ssum.w += u.w;
        }
        reinterpret_cast<float4*>(g_rop + (size_t)bi * MEM_D)[t] = ssum;
    }
    __syncthreads();                          // rop stores issued
    if (t == 0) {
        __threadfence();
        atomicAdd(&g_cnt3[b], 1);
    }

    // ============ Epilogue: ch==0 block finishes the batch ============
    if (ch != 0) return;
    if (t == 0) {
        while (atomicAdd(&g_cnt3[b], 0) < CPB) __nanosleep(32);
        __threadfence();
    }
    __syncthreads();

    // sr (reuse srq) = sum_ch rop + s * v
    if (t < MEM_D) {
        float accr = sval * sv[t];
        const float* rp = g_rop + (size_t)b * CPB * MEM_D + t;
#pragma unroll
        for (int c = 0; c < CPB; c++) accr += __ldcg(rp + c * MEM_D);
        srq[t] = accr;
    }
    if (t == 0) {                             // reset counters for next replay
        g_cnt1[b] = 0; g_cnt2[b] = 0; g_cnt3[b] = 0;
    }
    __syncthreads();

    // out[b, t] = bro[t] + sum_d sr[d] * Wro[d*IN_D + t]   (256 threads)
    {
        float a0 = 0.f, a1 = 0.f;
#pragma unroll 8
        for (int d = 0; d < MEM_D; d += 2) {
            a0 = fmaf(srq[d],     Wro[(d)     * IN_D + t], a0);
            a1 = fmaf(srq[d + 1], Wro[(d + 1) * IN_D + t], a1);
        }
        out[b * IN_D + t] = a0 + a1 + bro[t];
    }
}

// ---------------------------------------------------------------------------
extern "C" void kernel_launch(void* const* d_in, const int* in_sizes, int n_in,
                              void* d_out, int out_size) {
    const float* x   = (const float*)d_in[0];
    const float* mem = (const float*)d_in[1];
    const float* Ww  = (const float*)d_in[2];
    const float* bw  = (const float*)d_in[3];
    const float* Wq  = (const float*)d_in[4];
    const float* bq  = (const float*)d_in[5];
    const float* Wr  = (const float*)d_in[6];
    const float* br  = (const float*)d_in[7];
    const float* Wro = (const float*)d_in[8];
    const float* bro = (const float*)d_in[9];
    float* out = (float*)d_out;

    proj_kernel<<<3 * BATCH * KQ, 128>>>(x, Ww, Wq, Wr);
    fused_kernel<<<BATCH * CPB, 256>>>(mem, bw, bq, br, Wro, bro, out);
}